// round 6
// baseline (speedup 1.0000x reference)
#include <cuda_runtime.h>

#define Bb 32768

#define OFF_KIJ 0
#define OFF_AIK 13107200
#define OFF_TJ  14417920
#define OFF_R   15728640
#define OFF_RT  28835840

static __device__ __forceinline__ int eidx(int i, int j) {
    return i * 9 + j - (j > i ? 1 : 0);
}
static __device__ __forceinline__ float4 f4fma(float a, float4 w, float4 acc) {
    acc.x = fmaf(a, w.x, acc.x);
    acc.y = fmaf(a, w.y, acc.y);
    acc.z = fmaf(a, w.z, acc.z);
    acc.w = fmaf(a, w.w, acc.w);
    return acc;
}
static __device__ __forceinline__ float dot4(float4 a, float4 b) {
    return a.x*b.x + a.y*b.y + a.z*b.z + a.w*b.w;
}
static __device__ __forceinline__ float lrelu(float v) {
    return v >= 0.f ? v : 0.01f * v;
}
// acc += (16-vec y) dot (16x4 slab of W1), W1 quads at base, stride 2 per c
static __device__ __forceinline__ float4 proj16(const float4* __restrict__ Wq, int base,
                                                float4 y0, float4 y1, float4 y2, float4 y3,
                                                float4 acc) {
    acc = f4fma(y0.x, Wq[base + 0],  acc);
    acc = f4fma(y0.y, Wq[base + 2],  acc);
    acc = f4fma(y0.z, Wq[base + 4],  acc);
    acc = f4fma(y0.w, Wq[base + 6],  acc);
    acc = f4fma(y1.x, Wq[base + 8],  acc);
    acc = f4fma(y1.y, Wq[base + 10], acc);
    acc = f4fma(y1.z, Wq[base + 12], acc);
    acc = f4fma(y1.w, Wq[base + 14], acc);
    acc = f4fma(y2.x, Wq[base + 16], acc);
    acc = f4fma(y2.y, Wq[base + 18], acc);
    acc = f4fma(y2.z, Wq[base + 20], acc);
    acc = f4fma(y2.w, Wq[base + 22], acc);
    acc = f4fma(y3.x, Wq[base + 24], acc);
    acc = f4fma(y3.y, Wq[base + 26], acc);
    acc = f4fma(y3.z, Wq[base + 28], acc);
    acc = f4fma(y3.w, Wq[base + 30], acc);
    return acc;
}

// word-offset helpers
#define SXW(h,k,j)  ((((h)*4+(k))*10+(j))*4)    // s_x  [hop][k][j][4]
#define Y1W(k,j)    ((k)*200+(j)*20)            // s_Y1 [k][j][20] (16 used)
#define ZW(k,j)     ((k)*120+(j)*12)            // s_z  [k][j][12] (8 used)

__global__ __launch_bounds__(128, 8) void gnn_kernel(
    const float* __restrict__ x,
    const float* __restrict__ ew,
    const float* __restrict__ eigen,
    const float* __restrict__ a0p,
    const float* __restrict__ W0,
    const float* __restrict__ b0,
    const float* __restrict__ W1,
    const float* __restrict__ b1,
    const float* __restrict__ bp,
    const float* __restrict__ cp,
    const float* __restrict__ ww,
    float* __restrict__ out)
{
    const int b = blockIdx.x;
    const int tid = threadIdx.x;

    __shared__ __align__(16) float s_w[4][90];
    __shared__ float s_dinv[4][10];
    __shared__ float s_A[4][10][10];
    __shared__ __align__(16) float s_x[640];    // hop-propagated inputs (3-wide, padded to 4)
    __shared__ __align__(16) float s_Y1[800];   // layer-1 output, rows padded to 20
    __shared__ __align__(16) float s_zA[480];   // Horner state ping
    __shared__ __align__(16) float s_zB[480];   // Horner state pong
    __shared__ __align__(16) float s_y[4][10][8];
    __shared__ __align__(16) float s_yw[4][10][8];
    __shared__ float s_pm[4][10];
    __shared__ float s_tk[4][10];
    __shared__ float s_eig[4];
    __shared__ __align__(16) float s_W0[192];   // [hop][3][16]
    __shared__ __align__(16) float s_W1[512];   // [hop][16][8]
    __shared__ __align__(16) float s_b0[16];
    __shared__ __align__(16) float s_b1[8];
    __shared__ __align__(16) float s_bp[8];
    __shared__ __align__(16) float s_cp[8];
    __shared__ __align__(16) float s_ww[64];
    __shared__ float s_a0;

    // ---- stage parameters (vectorized) ----
    if (tid < 48) reinterpret_cast<float4*>(s_W0)[tid] =
        reinterpret_cast<const float4*>(W0)[tid];
    reinterpret_cast<float4*>(s_W1)[tid] =
        reinterpret_cast<const float4*>(W1)[tid];
    if (tid < 16)                   s_b0[tid]      = b0[tid];
    else if (tid < 24)              s_b1[tid - 16] = b1[tid - 16];
    else if (tid < 32)              s_bp[tid - 24] = bp[tid - 24];
    else if (tid < 40)              s_cp[tid - 32] = cp[tid - 32];
    else if (tid == 40)             s_a0           = a0p[0];
    else if (tid >= 44 && tid < 48) s_eig[tid - 44] = eigen[(tid - 44) * Bb + b];
    if (tid >= 64) s_ww[tid - 64] = ww[tid - 64];

    {
        // ew: 4 groups x 90 floats -> 4 x 45 float2
        const float2* ewb2 = reinterpret_cast<const float2*>(ew + (size_t)b * 90);
        for (int idx = tid; idx < 180; idx += 128) {
            int k = idx / 45, e = idx % 45;
            reinterpret_cast<float2*>(s_w[k])[e] = ewb2[(size_t)k * (Bb * 45) + e];
        }
    }
    {
        // x: 4 groups x 30 floats -> 4 x 15 float2
        const float2* xb2 = reinterpret_cast<const float2*>(x + (size_t)b * 30);
        if (tid < 60) {
            int k = tid / 15, t = tid % 15;
            float2 v = xb2[(size_t)k * (Bb * 15) + t];
            int r0 = 2 * t, r1 = 2 * t + 1;
            int j0 = r0 / 3, c0 = r0 % 3;
            int j1 = r1 / 3, c1 = r1 % 3;
            s_x[(k * 10 + j0) * 4 + c0] = v.x;
            s_x[(k * 10 + j1) * 4 + c1] = v.y;
            if (c0 == 2) s_pm[k][j0] = fmaxf(v.x, 0.0f);
            if (c1 == 2) s_pm[k][j1] = fmaxf(v.y, 0.0f);
        }
    }
    __syncthreads();

    // ---- degree + dinv ----
    if (tid < 40) {
        int k = tid / 10, j = tid % 10;
        float d = 0.f;
        #pragma unroll
        for (int i = 0; i < 10; i++)
            if (i != j) d += s_w[k][eidx(i, j)];
        s_dinv[k][j] = (d > 0.f) ? rsqrtf(d) : 0.f;
    }
    __syncthreads();

    // ---- normalized adjacency (shared only; R/RT stores deferred to warp 3) ----
    if (tid < 100) {
        const int n = tid / 10, m = tid % 10;
        const bool diag = (n == m);
        const int e_nm = diag ? 0 : eidx(n, m);
        #pragma unroll
        for (int k = 0; k < 4; k++) {
            float wnm = diag ? 0.f : s_w[k][e_nm];
            s_A[k][n][m] = wnm * s_dinv[k][n] * s_dinv[k][m];
        }
    }
    __syncthreads();

    // ================= layer-1 hop propagation (3-wide) =================
    const int k1 = tid / 30;
    const int r1 = tid % 30;
    const int j1 = r1 / 3;
    const int c1 = r1 % 3;
    float acol1[10];
    if (tid < 120) {
        #pragma unroll
        for (int i = 0; i < 10; i++) acol1[i] = s_A[k1][i][j1];
    }
    #pragma unroll
    for (int hk = 0; hk < 3; hk++) {
        if (tid < 120) {
            const float* src = &s_x[SXW(hk, k1, 0) + c1];
            float s = 0.f;
            #pragma unroll
            for (int i = 0; i < 10; i++) s = fmaf(acol1[i], src[i * 4], s);
            s_x[SXW(hk + 1, k1, j1) + c1] = s;
        }
        __syncthreads();
    }

    // ---- common 80-thread mapping: (k2, j2, h2) ----
    const int k2 = tid / 20;
    const int r2 = tid % 20;
    const int j2 = r2 >> 1;
    const int h2 = r2 & 1;
    const bool act = (tid < 80);

    // ================= layer-1 projection =================
    if (act) {
        const float4* W0q = reinterpret_cast<const float4*>(s_W0);
        float4 acc0 = make_float4(0.f, 0.f, 0.f, 0.f);
        float4 acc1 = make_float4(0.f, 0.f, 0.f, 0.f);
        #pragma unroll
        for (int hop = 0; hop < 4; hop++) {
            float4 xv = *reinterpret_cast<const float4*>(&s_x[SXW(hop, k2, j2)]);
            int base = hop * 12 + h2 * 2;
            acc0 = f4fma(xv.x, W0q[base + 0], acc0);
            acc1 = f4fma(xv.x, W0q[base + 1], acc1);
            acc0 = f4fma(xv.y, W0q[base + 4], acc0);
            acc1 = f4fma(xv.y, W0q[base + 5], acc1);
            acc0 = f4fma(xv.z, W0q[base + 8], acc0);
            acc1 = f4fma(xv.z, W0q[base + 9], acc1);
        }
        float4 bb0 = reinterpret_cast<const float4*>(s_b0)[h2 * 2];
        float4 bb1 = reinterpret_cast<const float4*>(s_b0)[h2 * 2 + 1];
        float4 v0 = make_float4(lrelu(acc0.x + bb0.x), lrelu(acc0.y + bb0.y),
                                lrelu(acc0.z + bb0.z), lrelu(acc0.w + bb0.w));
        float4 v1 = make_float4(lrelu(acc1.x + bb1.x), lrelu(acc1.y + bb1.y),
                                lrelu(acc1.z + bb1.z), lrelu(acc1.w + bb1.w));
        float* yr = &s_Y1[Y1W(k2, j2) + h2 * 8];
        reinterpret_cast<float4*>(yr)[0] = v0;
        reinterpret_cast<float4*>(yr)[1] = v1;
    }
    __syncthreads();

    // ================= layer-2, Horner form =================
    // Warps 0-2 (tid<80): Horner init (proj16 hop 3).
    // Warp 3 (tid>=96): R / R_t global stores, overlapped with compute.
    const float4* W1q = reinterpret_cast<const float4*>(s_W1);
    float acol2[10];
    float4 y0, y1, y2, y3;
    if (act) {
        #pragma unroll
        for (int i = 0; i < 10; i++) acol2[i] = s_A[k2][i][j2];
        const float4* yq = reinterpret_cast<const float4*>(&s_Y1[Y1W(k2, j2)]);
        y0 = yq[0]; y1 = yq[1]; y2 = yq[2]; y3 = yq[3];
        float4 acc = make_float4(0.f, 0.f, 0.f, 0.f);
        acc = proj16(W1q, 3 * 32 + h2, y0, y1, y2, y3, acc);
        *reinterpret_cast<float4*>(&s_zA[ZW(k2, j2) + h2 * 4]) = acc;
    } else if (tid >= 96) {
        const int lane = tid - 96;
        #pragma unroll
        for (int it = 0; it < 7; it++) {
            int item = lane + it * 32;           // 0..199 valid
            if (item < 200) {
                int isrt = (item >= 100);
                int rq = item - isrt * 100;
                int k = rq / 25, q = rq % 25;
                float e = s_eig[k];
                int r = q * 4;
                float4 v;
                {
                    int n0 = r / 10,       m0 = r % 10;
                    int n1 = (r + 1) / 10, m1 = (r + 1) % 10;
                    int n2 = (r + 2) / 10, m2 = (r + 2) % 10;
                    int n3 = (r + 3) / 10, m3 = (r + 3) % 10;
                    v.x = (n0 == m0) ? 0.f : s_w[k][isrt ? eidx(m0, n0) : eidx(n0, m0)] * e;
                    v.y = (n1 == m1) ? 0.f : s_w[k][isrt ? eidx(m1, n1) : eidx(n1, m1)] * e;
                    v.z = (n2 == m2) ? 0.f : s_w[k][isrt ? eidx(m2, n2) : eidx(n2, m2)] * e;
                    v.w = (n3 == m3) ? 0.f : s_w[k][isrt ? eidx(m3, n3) : eidx(n3, m3)] * e;
                }
                float* dst = out + (isrt ? OFF_RT : OFF_R)
                           + (size_t)k * (Bb * 100) + (size_t)b * 100 + r;
                *reinterpret_cast<float4*>(dst) = v;
            }
        }
    }
    __syncthreads();

    float* zsrc = s_zA;
    float* zdst = s_zB;
    #pragma unroll
    for (int hop = 2; hop >= 1; hop--) {
        if (act) {
            float4 agg = make_float4(0.f, 0.f, 0.f, 0.f);
            const float* zp = &zsrc[ZW(k2, 0) + h2 * 4];
            #pragma unroll
            for (int i = 0; i < 10; i++) {
                float4 zv = *reinterpret_cast<const float4*>(&zp[i * 12]);
                agg = f4fma(acol2[i], zv, agg);
            }
            agg = proj16(W1q, hop * 32 + h2, y0, y1, y2, y3, agg);
            *reinterpret_cast<float4*>(&zdst[ZW(k2, j2) + h2 * 4]) = agg;
        }
        __syncthreads();
        float* t = zsrc; zsrc = zdst; zdst = t;
    }
    if (act) {
        float4 agg = make_float4(0.f, 0.f, 0.f, 0.f);
        const float* zp = &zsrc[ZW(k2, 0) + h2 * 4];
        #pragma unroll
        for (int i = 0; i < 10; i++) {
            float4 zv = *reinterpret_cast<const float4*>(&zp[i * 12]);
            agg = f4fma(acol2[i], zv, agg);
        }
        agg = proj16(W1q, 0 * 32 + h2, y0, y1, y2, y3, agg);
        float4 bb = reinterpret_cast<const float4*>(s_b1)[h2];
        float4 v = make_float4(lrelu(agg.x + bb.x), lrelu(agg.y + bb.y),
                               lrelu(agg.z + bb.z), lrelu(agg.w + bb.w));
        reinterpret_cast<float4*>(s_y[k2][j2])[h2] = v;
    }
    __syncthreads();

    // ================= epilogue =================
    if (act) {
        const float4* yv = reinterpret_cast<const float4*>(s_y[k2][j2]);
        float4 ya = yv[0], yb = yv[1];
        const float4* wwv = reinterpret_cast<const float4*>(s_ww);
        int d = h2 * 4;
        float4 r;
        r.x = dot4(ya, wwv[(d + 0) * 2]) + dot4(yb, wwv[(d + 0) * 2 + 1]);
        r.y = dot4(ya, wwv[(d + 1) * 2]) + dot4(yb, wwv[(d + 1) * 2 + 1]);
        r.z = dot4(ya, wwv[(d + 2) * 2]) + dot4(yb, wwv[(d + 2) * 2 + 1]);
        r.w = dot4(ya, wwv[(d + 3) * 2]) + dot4(yb, wwv[(d + 3) * 2 + 1]);
        reinterpret_cast<float4*>(s_yw[k2][j2])[h2] = r;
    }
    // a_ik, t_k
    if (tid < 40) {
        int k = tid / 10, j = tid % 10;
        const float4* yv = reinterpret_cast<const float4*>(s_y[k][j]);
        float4 ya = yv[0], yb = yv[1];
        const float4* bpv = reinterpret_cast<const float4*>(s_bp);
        const float4* cpv = reinterpret_cast<const float4*>(s_cp);
        float ay = dot4(ya, bpv[0]) + dot4(yb, bpv[1]);
        float ty = dot4(ya, cpv[0]) + dot4(yb, cpv[1]);
        out[OFF_AIK + (size_t)k * (Bb * 10) + (size_t)b * 10 + j] = s_a0 + fmaxf(ay, 0.f);
        float tk = ty * (1.0f - s_pm[k][j]);
        if (tk == 0.0f) tk = -10000000000.0f;
        s_tk[k][j] = tk;
    }
    __syncthreads();

    // t_j = softmax over K
    if (tid < 10) {
        float t0 = s_tk[0][tid], t1 = s_tk[1][tid], t2 = s_tk[2][tid], t3 = s_tk[3][tid];
        float m = fmaxf(fmaxf(t0, t1), fmaxf(t2, t3));
        float e0 = __expf(t0 - m), e1 = __expf(t1 - m);
        float e2 = __expf(t2 - m), e3 = __expf(t3 - m);
        float inv = 1.f / (e0 + e1 + e2 + e3);
        float* pt = out + OFF_TJ + (size_t)b * 10 + tid;
        pt[0]            = e0 * inv;
        pt[Bb * 10]      = e1 * inv;
        pt[2 * Bb * 10]  = e2 * inv;
        pt[3 * Bb * 10]  = e3 * inv;
    }

    // K_y + softmax over K -> k_ij
    if (tid < 100) {
        int n = tid / 10, m = tid % 10;
        float kv[4];
        #pragma unroll
        for (int k = 0; k < 4; k++) {
            const float4* av = reinterpret_cast<const float4*>(s_yw[k][n]);
            const float4* cv = reinterpret_cast<const float4*>(s_y[k][m]);
            kv[k] = dot4(av[0], cv[0]) + dot4(av[1], cv[1]);
        }
        float mx = fmaxf(fmaxf(kv[0], kv[1]), fmaxf(kv[2], kv[3]));
        float e[4];
        float ssum = 0.f;
        #pragma unroll
        for (int k = 0; k < 4; k++) { e[k] = __expf(kv[k] - mx); ssum += e[k]; }
        float inv = 1.f / ssum;
        float* pk = out + OFF_KIJ + (size_t)b * 100 + tid;
        #pragma unroll
        for (int k = 0; k < 4; k++)
            pk[(size_t)k * (Bb * 100)] = e[k] * inv;
    }
}

extern "C" void kernel_launch(void* const* d_in, const int* in_sizes, int n_in,
                              void* d_out, int out_size) {
    (void)out_size;
    const float* x  = (const float*)d_in[0];
    const float* ew = (const float*)d_in[2];
    int base = 3;
    if (n_in >= 15 && in_sizes[3] == 1 && in_sizes[4] == 1 && in_sizes[5] == 1) base = 6;
    const float* eigen = (const float*)d_in[base + 0];
    const float* a0    = (const float*)d_in[base + 1];
    const float* W0    = (const float*)d_in[base + 2];
    const float* b0    = (const float*)d_in[base + 3];
    const float* W1    = (const float*)d_in[base + 4];
    const float* b1    = (const float*)d_in[base + 5];
    const float* bp    = (const float*)d_in[base + 6];
    const float* cp    = (const float*)d_in[base + 7];
    const float* ww    = (const float*)d_in[base + 8];

    gnn_kernel<<<Bb, 128>>>(x, ew, eigen, a0, W0, b0, W1, b1, bp, cp, ww, (float*)d_out);
}

// round 7
// speedup vs baseline: 1.1804x; 1.1804x over previous
#include <cuda_runtime.h>

#define Bb 32768

#define OFF_KIJ 0
#define OFF_AIK 13107200
#define OFF_TJ  14417920
#define OFF_R   15728640
#define OFF_RT  28835840

static __device__ __forceinline__ int eidx(int i, int j) {
    return i * 9 + j - (j > i ? 1 : 0);
}
static __device__ __forceinline__ float4 f4fma(float a, float4 w, float4 acc) {
    acc.x = fmaf(a, w.x, acc.x);
    acc.y = fmaf(a, w.y, acc.y);
    acc.z = fmaf(a, w.z, acc.z);
    acc.w = fmaf(a, w.w, acc.w);
    return acc;
}
static __device__ __forceinline__ float dot4(float4 a, float4 b) {
    return a.x*b.x + a.y*b.y + a.z*b.z + a.w*b.w;
}
static __device__ __forceinline__ float lrelu(float v) {
    return v >= 0.f ? v : 0.01f * v;
}
// acc += (16-vec y) dot (16x4 slab of W1), W1 quads at base, stride 2 per c
static __device__ __forceinline__ float4 proj16(const float4* __restrict__ Wq, int base,
                                                float4 y0, float4 y1, float4 y2, float4 y3,
                                                float4 acc) {
    acc = f4fma(y0.x, Wq[base + 0],  acc);
    acc = f4fma(y0.y, Wq[base + 2],  acc);
    acc = f4fma(y0.z, Wq[base + 4],  acc);
    acc = f4fma(y0.w, Wq[base + 6],  acc);
    acc = f4fma(y1.x, Wq[base + 8],  acc);
    acc = f4fma(y1.y, Wq[base + 10], acc);
    acc = f4fma(y1.z, Wq[base + 12], acc);
    acc = f4fma(y1.w, Wq[base + 14], acc);
    acc = f4fma(y2.x, Wq[base + 16], acc);
    acc = f4fma(y2.y, Wq[base + 18], acc);
    acc = f4fma(y2.z, Wq[base + 20], acc);
    acc = f4fma(y2.w, Wq[base + 22], acc);
    acc = f4fma(y3.x, Wq[base + 24], acc);
    acc = f4fma(y3.y, Wq[base + 26], acc);
    acc = f4fma(y3.z, Wq[base + 28], acc);
    acc = f4fma(y3.w, Wq[base + 30], acc);
    return acc;
}

// word-offset helpers
#define SXW(h,k,j)  ((((h)*4+(k))*10+(j))*4)    // s_x  [hop][k][j][4]
#define Y1W(k,j)    ((k)*200+(j)*20)            // s_Y1 [k][j][20] (16 used)
#define ZW(k,j)     ((k)*120+(j)*12)            // s_z  [k][j][12] (8 used)

__global__ __launch_bounds__(128, 8) void gnn_kernel(
    const float* __restrict__ x,
    const float* __restrict__ ew,
    const float* __restrict__ eigen,
    const float* __restrict__ a0p,
    const float* __restrict__ W0,
    const float* __restrict__ b0,
    const float* __restrict__ W1,
    const float* __restrict__ b1,
    const float* __restrict__ bp,
    const float* __restrict__ cp,
    const float* __restrict__ ww,
    float* __restrict__ out)
{
    const int b = blockIdx.x;
    const int tid = threadIdx.x;

    __shared__ __align__(16) float s_w[4][90];
    __shared__ float s_dinv[4][10];
    __shared__ float s_A[4][10][10];
    __shared__ __align__(16) float s_x[640];    // hop-propagated inputs (3-wide, padded to 4)
    __shared__ __align__(16) float s_Y1[800];   // layer-1 output, rows padded to 20
    __shared__ __align__(16) float s_zA[480];   // Horner state ping
    __shared__ __align__(16) float s_zB[480];   // Horner state pong
    __shared__ __align__(16) float s_y[4][10][8];
    __shared__ __align__(16) float s_yw[4][10][8];
    __shared__ float s_pm[4][10];
    __shared__ float s_tk[4][10];
    __shared__ float s_eig[4];
    __shared__ __align__(16) float s_W0[192];   // [hop][3][16]
    __shared__ __align__(16) float s_W1[512];   // [hop][16][8]
    __shared__ __align__(16) float s_b0[16];
    __shared__ __align__(16) float s_b1[8];
    __shared__ __align__(16) float s_bp[8];
    __shared__ __align__(16) float s_cp[8];
    __shared__ __align__(16) float s_ww[64];
    __shared__ float s_a0;

    // ---- stage parameters (vectorized) ----
    if (tid < 48) reinterpret_cast<float4*>(s_W0)[tid] =
        reinterpret_cast<const float4*>(W0)[tid];
    reinterpret_cast<float4*>(s_W1)[tid] =
        reinterpret_cast<const float4*>(W1)[tid];
    if (tid < 16)                   s_b0[tid]      = b0[tid];
    else if (tid < 24)              s_b1[tid - 16] = b1[tid - 16];
    else if (tid < 32)              s_bp[tid - 24] = bp[tid - 24];
    else if (tid < 40)              s_cp[tid - 32] = cp[tid - 32];
    else if (tid == 40)             s_a0           = a0p[0];
    else if (tid >= 44 && tid < 48) s_eig[tid - 44] = eigen[(tid - 44) * Bb + b];
    if (tid >= 64) s_ww[tid - 64] = ww[tid - 64];

    {
        // ew: 4 groups x 90 floats -> 4 x 45 float2
        const float2* ewb2 = reinterpret_cast<const float2*>(ew + (size_t)b * 90);
        for (int idx = tid; idx < 180; idx += 128) {
            int k = idx / 45, e = idx % 45;
            reinterpret_cast<float2*>(s_w[k])[e] = ewb2[(size_t)k * (Bb * 45) + e];
        }
    }
    {
        // x: 4 groups x 30 floats -> 4 x 15 float2
        const float2* xb2 = reinterpret_cast<const float2*>(x + (size_t)b * 30);
        if (tid < 60) {
            int k = tid / 15, t = tid % 15;
            float2 v = xb2[(size_t)k * (Bb * 15) + t];
            int r0 = 2 * t, r1 = 2 * t + 1;
            int j0 = r0 / 3, c0 = r0 % 3;
            int j1 = r1 / 3, c1 = r1 % 3;
            s_x[(k * 10 + j0) * 4 + c0] = v.x;
            s_x[(k * 10 + j1) * 4 + c1] = v.y;
            if (c0 == 2) s_pm[k][j0] = fmaxf(v.x, 0.0f);
            if (c1 == 2) s_pm[k][j1] = fmaxf(v.y, 0.0f);
        }
    }
    __syncthreads();

    // ---- degree + dinv ----
    if (tid < 40) {
        int k = tid / 10, j = tid % 10;
        float d = 0.f;
        #pragma unroll
        for (int i = 0; i < 10; i++)
            if (i != j) d += s_w[k][eidx(i, j)];
        s_dinv[k][j] = (d > 0.f) ? rsqrtf(d) : 0.f;
    }
    __syncthreads();

    // ---- normalized adjacency + R / R_t : fixed (n,m) per thread, k unrolled ----
    if (tid < 100) {
        const int n = tid / 10, m = tid % 10;
        const bool diag = (n == m);
        const int e_nm = diag ? 0 : eidx(n, m);
        const int e_mn = diag ? 0 : eidx(m, n);
        float* outR  = out + OFF_R  + (size_t)b * 100 + tid;
        float* outRT = out + OFF_RT + (size_t)b * 100 + tid;
        #pragma unroll
        for (int k = 0; k < 4; k++) {
            float wnm = diag ? 0.f : s_w[k][e_nm];
            float wmn = diag ? 0.f : s_w[k][e_mn];
            s_A[k][n][m] = wnm * s_dinv[k][n] * s_dinv[k][m];
            float e = s_eig[k];
            outR [(size_t)k * (Bb * 100)] = wnm * e;
            outRT[(size_t)k * (Bb * 100)] = wmn * e;
        }
    }
    __syncthreads();

    // ================= layer-1 hop propagation (3-wide) =================
    const int k1 = tid / 30;
    const int r1 = tid % 30;
    const int j1 = r1 / 3;
    const int c1 = r1 % 3;
    float acol1[10];
    if (tid < 120) {
        #pragma unroll
        for (int i = 0; i < 10; i++) acol1[i] = s_A[k1][i][j1];
    }
    #pragma unroll
    for (int hk = 0; hk < 3; hk++) {
        if (tid < 120) {
            const float* src = &s_x[SXW(hk, k1, 0) + c1];
            float s = 0.f;
            #pragma unroll
            for (int i = 0; i < 10; i++) s = fmaf(acol1[i], src[i * 4], s);
            s_x[SXW(hk + 1, k1, j1) + c1] = s;
        }
        __syncthreads();
    }

    // ---- common 80-thread mapping: (k2, j2, h2) ----
    const int k2 = tid / 20;
    const int r2 = tid % 20;
    const int j2 = r2 >> 1;
    const int h2 = r2 & 1;
    const bool act = (tid < 80);

    // ================= layer-1 projection =================
    if (act) {
        const float4* W0q = reinterpret_cast<const float4*>(s_W0);
        float4 acc0 = make_float4(0.f, 0.f, 0.f, 0.f);
        float4 acc1 = make_float4(0.f, 0.f, 0.f, 0.f);
        #pragma unroll
        for (int hop = 0; hop < 4; hop++) {
            float4 xv = *reinterpret_cast<const float4*>(&s_x[SXW(hop, k2, j2)]);
            int base = hop * 12 + h2 * 2;
            acc0 = f4fma(xv.x, W0q[base + 0], acc0);
            acc1 = f4fma(xv.x, W0q[base + 1], acc1);
            acc0 = f4fma(xv.y, W0q[base + 4], acc0);
            acc1 = f4fma(xv.y, W0q[base + 5], acc1);
            acc0 = f4fma(xv.z, W0q[base + 8], acc0);
            acc1 = f4fma(xv.z, W0q[base + 9], acc1);
        }
        float4 bb0 = reinterpret_cast<const float4*>(s_b0)[h2 * 2];
        float4 bb1 = reinterpret_cast<const float4*>(s_b0)[h2 * 2 + 1];
        float4 v0 = make_float4(lrelu(acc0.x + bb0.x), lrelu(acc0.y + bb0.y),
                                lrelu(acc0.z + bb0.z), lrelu(acc0.w + bb0.w));
        float4 v1 = make_float4(lrelu(acc1.x + bb1.x), lrelu(acc1.y + bb1.y),
                                lrelu(acc1.z + bb1.z), lrelu(acc1.w + bb1.w));
        float* yr = &s_Y1[Y1W(k2, j2) + h2 * 8];
        reinterpret_cast<float4*>(yr)[0] = v0;
        reinterpret_cast<float4*>(yr)[1] = v1;
    }
    __syncthreads();

    // ================= layer-2, Horner form =================
    const float4* W1q = reinterpret_cast<const float4*>(s_W1);
    float acol2[10];
    float4 y0, y1, y2, y3;
    if (act) {
        #pragma unroll
        for (int i = 0; i < 10; i++) acol2[i] = s_A[k2][i][j2];
        const float4* yq = reinterpret_cast<const float4*>(&s_Y1[Y1W(k2, j2)]);
        y0 = yq[0]; y1 = yq[1]; y2 = yq[2]; y3 = yq[3];
        float4 acc = make_float4(0.f, 0.f, 0.f, 0.f);
        acc = proj16(W1q, 3 * 32 + h2, y0, y1, y2, y3, acc);
        *reinterpret_cast<float4*>(&s_zA[ZW(k2, j2) + h2 * 4]) = acc;
    }
    __syncthreads();

    float* zsrc = s_zA;
    float* zdst = s_zB;
    #pragma unroll
    for (int hop = 2; hop >= 1; hop--) {
        if (act) {
            float4 agg = make_float4(0.f, 0.f, 0.f, 0.f);
            const float* zp = &zsrc[ZW(k2, 0) + h2 * 4];
            #pragma unroll
            for (int i = 0; i < 10; i++) {
                float4 zv = *reinterpret_cast<const float4*>(&zp[i * 12]);
                agg = f4fma(acol2[i], zv, agg);
            }
            agg = proj16(W1q, hop * 32 + h2, y0, y1, y2, y3, agg);
            *reinterpret_cast<float4*>(&zdst[ZW(k2, j2) + h2 * 4]) = agg;
        }
        __syncthreads();
        float* t = zsrc; zsrc = zdst; zdst = t;
    }
    if (act) {
        float4 agg = make_float4(0.f, 0.f, 0.f, 0.f);
        const float* zp = &zsrc[ZW(k2, 0) + h2 * 4];
        #pragma unroll
        for (int i = 0; i < 10; i++) {
            float4 zv = *reinterpret_cast<const float4*>(&zp[i * 12]);
            agg = f4fma(acol2[i], zv, agg);
        }
        agg = proj16(W1q, 0 * 32 + h2, y0, y1, y2, y3, agg);
        float4 bb = reinterpret_cast<const float4*>(s_b1)[h2];
        float4 v = make_float4(lrelu(agg.x + bb.x), lrelu(agg.y + bb.y),
                               lrelu(agg.z + bb.z), lrelu(agg.w + bb.w));
        reinterpret_cast<float4*>(s_y[k2][j2])[h2] = v;
    }
    __syncthreads();

    // ================= epilogue =================
    if (act) {
        const float4* yv = reinterpret_cast<const float4*>(s_y[k2][j2]);
        float4 ya = yv[0], yb = yv[1];
        const float4* wwv = reinterpret_cast<const float4*>(s_ww);
        int d = h2 * 4;
        float4 r;
        r.x = dot4(ya, wwv[(d + 0) * 2]) + dot4(yb, wwv[(d + 0) * 2 + 1]);
        r.y = dot4(ya, wwv[(d + 1) * 2]) + dot4(yb, wwv[(d + 1) * 2 + 1]);
        r.z = dot4(ya, wwv[(d + 2) * 2]) + dot4(yb, wwv[(d + 2) * 2 + 1]);
        r.w = dot4(ya, wwv[(d + 3) * 2]) + dot4(yb, wwv[(d + 3) * 2 + 1]);
        reinterpret_cast<float4*>(s_yw[k2][j2])[h2] = r;
    }
    // a_ik, t_k
    if (tid < 40) {
        int k = tid / 10, j = tid % 10;
        const float4* yv = reinterpret_cast<const float4*>(s_y[k][j]);
        float4 ya = yv[0], yb = yv[1];
        const float4* bpv = reinterpret_cast<const float4*>(s_bp);
        const float4* cpv = reinterpret_cast<const float4*>(s_cp);
        float ay = dot4(ya, bpv[0]) + dot4(yb, bpv[1]);
        float ty = dot4(ya, cpv[0]) + dot4(yb, cpv[1]);
        out[OFF_AIK + (size_t)k * (Bb * 10) + (size_t)b * 10 + j] = s_a0 + fmaxf(ay, 0.f);
        float tk = ty * (1.0f - s_pm[k][j]);
        if (tk == 0.0f) tk = -10000000000.0f;
        s_tk[k][j] = tk;
    }
    __syncthreads();

    // t_j = softmax over K
    if (tid < 10) {
        float t0 = s_tk[0][tid], t1 = s_tk[1][tid], t2 = s_tk[2][tid], t3 = s_tk[3][tid];
        float m = fmaxf(fmaxf(t0, t1), fmaxf(t2, t3));
        float e0 = __expf(t0 - m), e1 = __expf(t1 - m);
        float e2 = __expf(t2 - m), e3 = __expf(t3 - m);
        float inv = 1.f / (e0 + e1 + e2 + e3);
        float* pt = out + OFF_TJ + (size_t)b * 10 + tid;
        pt[0]            = e0 * inv;
        pt[Bb * 10]      = e1 * inv;
        pt[2 * Bb * 10]  = e2 * inv;
        pt[3 * Bb * 10]  = e3 * inv;
    }

    // K_y + softmax over K -> k_ij
    if (tid < 100) {
        int n = tid / 10, m = tid % 10;
        float kv[4];
        #pragma unroll
        for (int k = 0; k < 4; k++) {
            const float4* av = reinterpret_cast<const float4*>(s_yw[k][n]);
            const float4* cv = reinterpret_cast<const float4*>(s_y[k][m]);
            kv[k] = dot4(av[0], cv[0]) + dot4(av[1], cv[1]);
        }
        float mx = fmaxf(fmaxf(kv[0], kv[1]), fmaxf(kv[2], kv[3]));
        float e[4];
        float ssum = 0.f;
        #pragma unroll
        for (int k = 0; k < 4; k++) { e[k] = __expf(kv[k] - mx); ssum += e[k]; }
        float inv = 1.f / ssum;
        float* pk = out + OFF_KIJ + (size_t)b * 100 + tid;
        #pragma unroll
        for (int k = 0; k < 4; k++)
            pk[(size_t)k * (Bb * 100)] = e[k] * inv;
    }
}

extern "C" void kernel_launch(void* const* d_in, const int* in_sizes, int n_in,
                              void* d_out, int out_size) {
    (void)out_size;
    const float* x  = (const float*)d_in[0];
    const float* ew = (const float*)d_in[2];
    int base = 3;
    if (n_in >= 15 && in_sizes[3] == 1 && in_sizes[4] == 1 && in_sizes[5] == 1) base = 6;
    const float* eigen = (const float*)d_in[base + 0];
    const float* a0    = (const float*)d_in[base + 1];
    const float* W0    = (const float*)d_in[base + 2];
    const float* b0    = (const float*)d_in[base + 3];
    const float* W1    = (const float*)d_in[base + 4];
    const float* b1    = (const float*)d_in[base + 5];
    const float* bp    = (const float*)d_in[base + 6];
    const float* cp    = (const float*)d_in[base + 7];
    const float* ww    = (const float*)d_in[base + 8];

    gnn_kernel<<<Bb, 128>>>(x, ew, eigen, a0, W0, b0, W1, b1, bp, cp, ww, (float*)d_out);
}